// round 5
// baseline (speedup 1.0000x reference)
#include <cuda_runtime.h>

#define BATCH 1024
#define FDIM 32
#define EMBED 8
#define HEADS 4
#define NBINS 1100
#define OUTD 16
#define FH (FDIM*HEADS)

typedef unsigned long long u64;

// Scratch (allocation-free: __device__ globals)
__device__ float2 g_q[FH * BATCH];
__device__ float2 g_k[FH * BATCH];
__device__ float2 g_v[FH * BATCH];
__device__ float g_o[BATCH * FDIM * EMBED];   // [B][256]

// ---- packed f32x2 helpers (Blackwell FFMA2 path, PTX-only) -----------------
__device__ __forceinline__ u64 pk(float lo, float hi) {
    u64 r; asm("mov.b64 %0, {%1, %2};" : "=l"(r) : "f"(lo), "f"(hi)); return r;
}
__device__ __forceinline__ void upk(u64 a, float& x, float& y) {
    asm("mov.b64 {%0, %1}, %2;" : "=f"(x), "=f"(y) : "l"(a));
}
__device__ __forceinline__ u64 fma2(u64 a, u64 b, u64 c) {
    u64 d; asm("fma.rn.f32x2 %0, %1, %2, %3;" : "=l"(d) : "l"(a), "l"(b), "l"(c)); return d;
}
__device__ __forceinline__ u64 mul2(u64 a, u64 b) {
    u64 d; asm("mul.rn.f32x2 %0, %1, %2;" : "=l"(d) : "l"(a), "l"(b)); return d;
}
__device__ __forceinline__ u64 add2(u64 a, u64 b) {
    u64 d; asm("add.rn.f32x2 %0, %1, %2;" : "=l"(d) : "l"(a), "l"(b)); return d;
}
// Two exps in ONE MUFU op: packed f32x2 score -> f16x2 -> ex2 -> f32x2.
__device__ __forceinline__ u64 ex2_h2p(u64 ss) {
    float s0, s1; upk(ss, s0, s1);
    unsigned hh, he;
    asm("cvt.rn.f16x2.f32 %0, %1, %2;" : "=r"(hh) : "f"(s1), "f"(s0));
    asm("ex2.approx.f16x2 %0, %1;" : "=r"(he) : "r"(hh));
    float e0, e1;
    asm("{.reg .b16 lo, hi;\n\t"
        "mov.b32 {lo, hi}, %2;\n\t"
        "cvt.f32.f16 %0, lo;\n\t"
        "cvt.f32.f16 %1, hi;}"
        : "=f"(e0), "=f"(e1) : "r"(he));
    return pk(e0, e1);
}

// Replicate jnp.linspace(MN,MX,NBINS) element: step*i + start, fp32 rounding
// at each op (no FMA contraction).
__device__ __forceinline__ float binv(int i) {
    const float step = 301.0f / 1099.0f;
    return __fadd_rn(__fmul_rn(step, (float)i), -1.0f);
}

// ---------------------------------------------------------------------------
// Stage A: bin search + embedding gather + QKV projection.
// grid (4, 32) x 256 threads (best measured config: 6.1us)
// ---------------------------------------------------------------------------
__global__ void stageA(const float* __restrict__ x, const float* __restrict__ emb,
                       const float* __restrict__ ipw, const float* __restrict__ ipb) {
    __shared__ float sw[192];
    __shared__ float sb[24];
    int tid = threadIdx.x;
    if (tid < 192) sw[tid] = ipw[tid];
    if (tid < 24)  sb[tid] = ipb[tid];
    __syncthreads();

    int f = blockIdx.y;
    int b = blockIdx.x * blockDim.x + tid;

    float xv = x[b * FDIM + f];
    float xc = fminf(fmaxf(xv, -1.0f), 300.0f);

    // searchsorted(bins, xc, 'left'): first i with bins[i] >= xc
    int i = (int)((xc + 1.0f) * (1099.0f / 301.0f));
    i = max(0, min(i, NBINS - 1));
    while (i > 0 && binv(i - 1) >= xc) --i;
    while (i < NBINS - 1 && binv(i) < xc) ++i;

    const float4* ep = (const float4*)(emb + ((size_t)f * NBINS + i) * EMBED);
    float4 e0 = ep[0], e1 = ep[1];
    float xe[8] = {e0.x, e0.y, e0.z, e0.w, e1.x, e1.y, e1.z, e1.w};

    float out[24];
#pragma unroll
    for (int r = 0; r < 24; ++r) {
        float acc = sb[r];
#pragma unroll
        for (int j = 0; j < 8; ++j) acc = fmaf(xe[j], sw[r * 8 + j], acc);
        out[r] = acc;
    }

#pragma unroll
    for (int h = 0; h < HEADS; ++h) {
        int o = (f * HEADS + h) * BATCH + b;
        g_q[o] = make_float2(out[h * 2],      out[h * 2 + 1]);
        g_k[o] = make_float2(out[8 + h * 2],  out[8 + h * 2 + 1]);
        g_v[o] = make_float2(out[16 + h * 2], out[16 + h * 2 + 1]);
    }
}

// ---------------------------------------------------------------------------
// Stage B: per-(f,h) attention over batch axis, hd=2, single-pass softmax.
// Packed f32x2 scores/accumulation; ALL exps via one-MUFU-op f16x2.
// Each thread computes TWO b values (b, b+512): every K/V shared load is
// reused twice -> fixed-pipe ops/b nearly halve.
// ---------------------------------------------------------------------------
__global__ void stageB() {
    // per c-pair: sA = {pk(k0e,k0o), pk(k1e,k1o)}, sB = {pk(v0e,v0o), pk(v1e,v1o)}
    __shared__ ulonglong2 sA[BATCH / 2];   // 8KB
    __shared__ ulonglong2 sB[BATCH / 2];   // 8KB
    int fh  = blockIdx.x;
    int tid = threadIdx.x;

    const float4* kp = (const float4*)(g_k + fh * BATCH);  // (k0e,k1e,k0o,k1o)
    const float4* vp = (const float4*)(g_v + fh * BATCH);
    for (int p = tid; p < BATCH / 2; p += 128) {
        float4 k = kp[p];
        float4 v = vp[p];
        sA[p] = make_ulonglong2(pk(k.x, k.z), pk(k.y, k.w));
        sB[p] = make_ulonglong2(pk(v.x, v.z), pk(v.y, v.w));
    }
    __syncthreads();

    int b0 = blockIdx.y * 128 + tid;     // 0..511
    int b1 = b0 + 512;
    float2 qa = g_q[fh * BATCH + b0];
    float2 qb = g_q[fh * BATCH + b1];
    // fold 1/sqrt(hd) and log2(e) into q so exp(s) == exp2(q'.k)
    const float C = 1.4426950408889634f * 0.70710678118654752f;
    u64 qa0 = pk(qa.x * C, qa.x * C), qa1 = pk(qa.y * C, qa.y * C);
    u64 qb0 = pk(qb.x * C, qb.x * C), qb1 = pk(qb.y * C, qb.y * C);
    u64 z = pk(0.f, 0.f);
    u64 dd0 = z, aa00 = z, aa01 = z;
    u64 dd1 = z, aa10 = z, aa11 = z;

#pragma unroll 8
    for (int p = 0; p < BATCH / 2; ++p) {
        ulonglong2 A  = sA[p];
        ulonglong2 Bv = sB[p];
        u64 e0 = ex2_h2p(fma2(qa0, A.x, mul2(qa1, A.y)));
        u64 e1 = ex2_h2p(fma2(qb0, A.x, mul2(qb1, A.y)));
        dd0  = add2(dd0, e0);
        aa00 = fma2(e0, Bv.x, aa00);
        aa01 = fma2(e0, Bv.y, aa01);
        dd1  = add2(dd1, e1);
        aa10 = fma2(e1, Bv.x, aa10);
        aa11 = fma2(e1, Bv.y, aa11);
    }

    int f = fh >> 2, h = fh & 3;
    {
        float d0, d1, a00, a01, a10, a11;
        upk(dd0, d0, d1); upk(aa00, a00, a01); upk(aa01, a10, a11);
        float inv = 1.0f / (d0 + d1);
        float* op = g_o + (size_t)b0 * (FDIM * EMBED) + f * EMBED + h * 2;
        op[0] = (a00 + a01) * inv;
        op[1] = (a10 + a11) * inv;
    }
    {
        float d0, d1, a00, a01, a10, a11;
        upk(dd1, d0, d1); upk(aa10, a00, a01); upk(aa11, a10, a11);
        float inv = 1.0f / (d0 + d1);
        float* op = g_o + (size_t)b1 * (FDIM * EMBED) + f * EMBED + h * 2;
        op[0] = (a00 + a01) * inv;
        op[1] = (a10 + a11) * inv;
    }
}

// ---------------------------------------------------------------------------
// Stage C: out_proj (8x8 per f) + linear (16x256) + softmax(16)
// grid 64 x 512 threads : one warp per batch row, lane = f
// ---------------------------------------------------------------------------
__global__ void stageC(const float* __restrict__ opw, const float* __restrict__ opb,
                       const float* __restrict__ lw,  const float* __restrict__ lb,
                       float* __restrict__ out) {
    __shared__ float sWo[64];
    __shared__ float sbo[8];
    __shared__ float sLw[256 * 16];     // transposed: [i][t]
    __shared__ float sLb[16];
    __shared__ float o2sh[16][256];     // one 256-vector per warp

    int tid = threadIdx.x;
    for (int idx = tid; idx < 256 * 16; idx += blockDim.x) {
        int i = idx >> 4, t = idx & 15;
        sLw[idx] = lw[t * 256 + i];
    }
    if (tid < 64) sWo[tid] = opw[tid];
    if (tid < 8)  sbo[tid] = opb[tid];
    if (tid < 16) sLb[tid] = lb[tid];
    __syncthreads();

    int w = tid >> 5, lane = tid & 31;
    int b = blockIdx.x * 16 + w;

    // lane l owns feature f = l
    const float4* op = (const float4*)(g_o + (size_t)b * 256 + lane * 8);
    float4 v0 = op[0], v1 = op[1];
    float o[8] = {v0.x, v0.y, v0.z, v0.w, v1.x, v1.y, v1.z, v1.w};

#pragma unroll
    for (int e = 0; e < 8; ++e) {
        float acc = sbo[e];
#pragma unroll
        for (int j = 0; j < 8; ++j) acc = fmaf(o[j], sWo[e * 8 + j], acc);
        o2sh[w][lane * 8 + e] = acc;
    }
    __syncwarp();

    if (lane < 16) {
        float acc = sLb[lane];
#pragma unroll 8
        for (int i = 0; i < 256; ++i)
            acc = fmaf(o2sh[w][i], sLw[i * 16 + lane], acc);

        // softmax over 16 lanes
        float m = acc;
#pragma unroll
        for (int off = 8; off; off >>= 1)
            m = fmaxf(m, __shfl_xor_sync(0xffffu, m, off, 16));
        float e = __expf(acc - m);
        float s = e;
#pragma unroll
        for (int off = 8; off; off >>= 1)
            s += __shfl_xor_sync(0xffffu, s, off, 16);
        out[b * OUTD + lane] = e / s;
    }
}

// ---------------------------------------------------------------------------
extern "C" void kernel_launch(void* const* d_in, const int* in_sizes, int n_in,
                              void* d_out, int out_size) {
    const float* x   = (const float*)d_in[0];   // (1024, 32)
    const float* emb = (const float*)d_in[1];   // (32, 1100, 8)
    const float* ipw = (const float*)d_in[2];   // (24, 8)
    const float* ipb = (const float*)d_in[3];   // (24,)
    const float* opw = (const float*)d_in[4];   // (8, 8)
    const float* opb = (const float*)d_in[5];   // (8,)
    const float* lw  = (const float*)d_in[6];   // (16, 256)
    const float* lb  = (const float*)d_in[7];   // (16,)
    float* out = (float*)d_out;                 // (1024, 16)

    stageA<<<dim3(BATCH / 256, FDIM), 256>>>(x, emb, ipw, ipb);
    stageB<<<dim3(FH, 4), 128>>>();
    stageC<<<BATCH / 16, 512>>>(opw, opb, lw, lb, out);
}

// round 6
// speedup vs baseline: 1.1722x; 1.1722x over previous
#include <cuda_runtime.h>

#define BATCH 1024
#define FDIM 32
#define EMBED 8
#define HEADS 4
#define NBINS 1100
#define OUTD 16
#define FH (FDIM*HEADS)

typedef unsigned long long u64;

// Scratch (allocation-free: __device__ globals)
__device__ float2 g_q[FH * BATCH];
__device__ float2 g_k[FH * BATCH];
__device__ float2 g_v[FH * BATCH];
__device__ float g_o[BATCH * FDIM * EMBED];   // [B][256]

// ---- packed f32x2 helpers (Blackwell FFMA2 path, PTX-only) -----------------
__device__ __forceinline__ u64 pk(float lo, float hi) {
    u64 r; asm("mov.b64 %0, {%1, %2};" : "=l"(r) : "f"(lo), "f"(hi)); return r;
}
__device__ __forceinline__ void upk(u64 a, float& x, float& y) {
    asm("mov.b64 {%0, %1}, %2;" : "=f"(x), "=f"(y) : "l"(a));
}
__device__ __forceinline__ u64 fma2(u64 a, u64 b, u64 c) {
    u64 d; asm("fma.rn.f32x2 %0, %1, %2, %3;" : "=l"(d) : "l"(a), "l"(b), "l"(c)); return d;
}
__device__ __forceinline__ u64 mul2(u64 a, u64 b) {
    u64 d; asm("mul.rn.f32x2 %0, %1, %2;" : "=l"(d) : "l"(a), "l"(b)); return d;
}
__device__ __forceinline__ u64 add2(u64 a, u64 b) {
    u64 d; asm("add.rn.f32x2 %0, %1, %2;" : "=l"(d) : "l"(a), "l"(b)); return d;
}
__device__ __forceinline__ float ex2f(float s) {
    float e; asm("ex2.approx.ftz.f32 %0, %1;" : "=f"(e) : "f"(s)); return e;
}

// Packed exp2 on the FMA pipe: 8 packed FMA-pipe ops + 4 ALU ops per 2 exps.
// Magic-constant range reduction, deg-4 Taylor on |r|<=0.5 (rel err <= 4e-5),
// 2^n scale via integer bit trick.
__device__ __forceinline__ u64 exp2_poly2(u64 x) {
    const float MAGIC = 12582912.0f;            // 2^23 + 2^22
    u64 t = add2(x, pk(MAGIC, MAGIC));          // n captured in mantissa
    u64 u = add2(t, pk(-MAGIC, -MAGIC));        // u = round(x)
    u64 r = fma2(u, pk(-1.0f, -1.0f), x);       // r = x - u, |r| <= 0.5
    u64 p = fma2(pk(0.00961813f, 0.00961813f), r, pk(0.05550411f, 0.05550411f));
    p = fma2(p, r, pk(0.24022651f, 0.24022651f));
    p = fma2(p, r, pk(0.69314718f, 0.69314718f));
    p = fma2(p, r, pk(1.0f, 1.0f));
    float tlo, thi; upk(t, tlo, thi);
    unsigned ilo = (__float_as_uint(tlo) << 23) + (127u << 23);   // bits of 2^n_lo
    unsigned ihi = (__float_as_uint(thi) << 23) + (127u << 23);
    return mul2(p, pk(__uint_as_float(ilo), __uint_as_float(ihi)));
}

// Replicate jnp.linspace(MN,MX,NBINS) element: step*i + start, fp32 rounding
// at each op (no FMA contraction).
__device__ __forceinline__ float binv(int i) {
    const float step = 301.0f / 1099.0f;
    return __fadd_rn(__fmul_rn(step, (float)i), -1.0f);
}

// ---------------------------------------------------------------------------
// Stage A: bin search + embedding gather + QKV projection.
// grid (8, 32) x 128 threads = 256 blocks: all 148 SMs covered
// ---------------------------------------------------------------------------
__global__ void stageA(const float* __restrict__ x, const float* __restrict__ emb,
                       const float* __restrict__ ipw, const float* __restrict__ ipb) {
    __shared__ float sw[192];
    __shared__ float sb[24];
    int tid = threadIdx.x;
    for (int i = tid; i < 192; i += 128) sw[i] = ipw[i];
    if (tid < 24) sb[tid] = ipb[tid];
    __syncthreads();

    int f = blockIdx.y;
    int b = blockIdx.x * 128 + tid;

    float xv = x[b * FDIM + f];
    float xc = fminf(fmaxf(xv, -1.0f), 300.0f);

    // searchsorted(bins, xc, 'left'): first i with bins[i] >= xc
    int i = (int)((xc + 1.0f) * (1099.0f / 301.0f));
    i = max(0, min(i, NBINS - 1));
    while (i > 0 && binv(i - 1) >= xc) --i;
    while (i < NBINS - 1 && binv(i) < xc) ++i;

    const float4* ep = (const float4*)(emb + ((size_t)f * NBINS + i) * EMBED);
    float4 e0 = ep[0], e1 = ep[1];
    float xe[8] = {e0.x, e0.y, e0.z, e0.w, e1.x, e1.y, e1.z, e1.w};

    float out[24];
#pragma unroll
    for (int r = 0; r < 24; ++r) {
        float acc = sb[r];
#pragma unroll
        for (int j = 0; j < 8; ++j) acc = fmaf(xe[j], sw[r * 8 + j], acc);
        out[r] = acc;
    }

#pragma unroll
    for (int h = 0; h < HEADS; ++h) {
        int o = (f * HEADS + h) * BATCH + b;
        g_q[o] = make_float2(out[h * 2],      out[h * 2 + 1]);
        g_k[o] = make_float2(out[8 + h * 2],  out[8 + h * 2 + 1]);
        g_v[o] = make_float2(out[16 + h * 2], out[16 + h * 2 + 1]);
    }
}

// ---------------------------------------------------------------------------
// Stage B: per-(f,h) attention over batch axis, hd=2, single-pass softmax.
// Packed f32x2 arithmetic. Branch-free structural pipe split: of every 8
// c-pairs, pair 0 computes its exps via the FMA-pipe polynomial, pairs 1-7
// via MUFU (MUFU 16 -> 14 cyc/pair, FMA 10 -> 12; balanced).
// ---------------------------------------------------------------------------
__global__ void stageB() {
    // per c-pair: sA = {pk(k0e,k0o), pk(k1e,k1o)}, sB = {pk(v0e,v0o), pk(v1e,v1o)}
    __shared__ ulonglong2 sA[BATCH / 2];   // 8KB
    __shared__ ulonglong2 sB[BATCH / 2];   // 8KB
    int fh  = blockIdx.x;
    int tid = threadIdx.x;

    const float4* kp = (const float4*)(g_k + fh * BATCH);  // (k0e,k1e,k0o,k1o)
    const float4* vp = (const float4*)(g_v + fh * BATCH);
    for (int p = tid; p < BATCH / 2; p += 128) {
        float4 k = kp[p];
        float4 v = vp[p];
        sA[p] = make_ulonglong2(pk(k.x, k.z), pk(k.y, k.w));
        sB[p] = make_ulonglong2(pk(v.x, v.z), pk(v.y, v.w));
    }
    __syncthreads();

    int b = blockIdx.y * 128 + tid;
    float2 q = g_q[fh * BATCH + b];
    // fold 1/sqrt(hd) and log2(e) into q so exp(s) == exp2(q'.k)
    const float C = 1.4426950408889634f * 0.70710678118654752f;
    float q0 = q.x * C, q1 = q.y * C;
    u64 qq0 = pk(q0, q0), qq1 = pk(q1, q1);
    u64 dd = pk(0.f, 0.f), aa0 = dd, aa1 = dd;

    for (int pb = 0; pb < BATCH / 2; pb += 8) {
        // pair 0: exps on the FMA pipe (no branch -- structural)
        {
            ulonglong2 A  = sA[pb];
            ulonglong2 Bv = sB[pb];
            u64 ee = exp2_poly2(fma2(qq0, A.x, mul2(qq1, A.y)));
            dd  = add2(dd, ee);
            aa0 = fma2(ee, Bv.x, aa0);
            aa1 = fma2(ee, Bv.y, aa1);
        }
        // pairs 1..7: exps on MUFU
#pragma unroll
        for (int j = 1; j < 8; ++j) {
            ulonglong2 A  = sA[pb + j];
            ulonglong2 Bv = sB[pb + j];
            u64 ss = fma2(qq0, A.x, mul2(qq1, A.y));
            float s0, s1; upk(ss, s0, s1);
            u64 ee = pk(ex2f(s0), ex2f(s1));
            dd  = add2(dd, ee);
            aa0 = fma2(ee, Bv.x, aa0);
            aa1 = fma2(ee, Bv.y, aa1);
        }
    }

    float d0, d1, a00, a01, a10, a11;
    upk(dd, d0, d1); upk(aa0, a00, a01); upk(aa1, a10, a11);
    float inv = 1.0f / (d0 + d1);
    int f = fh >> 2, h = fh & 3;
    float* op = g_o + (size_t)b * (FDIM * EMBED) + f * EMBED + h * 2;
    op[0] = (a00 + a01) * inv;
    op[1] = (a10 + a11) * inv;
}

// ---------------------------------------------------------------------------
// Stage C: out_proj (8x8 per f) + linear (16x256) + softmax(16)
// grid 64 x 512 threads : one warp per batch row, lane = f
// ---------------------------------------------------------------------------
__global__ void stageC(const float* __restrict__ opw, const float* __restrict__ opb,
                       const float* __restrict__ lw,  const float* __restrict__ lb,
                       float* __restrict__ out) {
    __shared__ float sWo[64];
    __shared__ float sbo[8];
    __shared__ float sLw[256 * 16];     // transposed: [i][t]
    __shared__ float sLb[16];
    __shared__ float o2sh[16][256];     // one 256-vector per warp

    int tid = threadIdx.x;
    for (int idx = tid; idx < 256 * 16; idx += blockDim.x) {
        int i = idx >> 4, t = idx & 15;
        sLw[idx] = lw[t * 256 + i];
    }
    if (tid < 64) sWo[tid] = opw[tid];
    if (tid < 8)  sbo[tid] = opb[tid];
    if (tid < 16) sLb[tid] = lb[tid];
    __syncthreads();

    int w = tid >> 5, lane = tid & 31;
    int b = blockIdx.x * 16 + w;

    // lane l owns feature f = l
    const float4* op = (const float4*)(g_o + (size_t)b * 256 + lane * 8);
    float4 v0 = op[0], v1 = op[1];
    float o[8] = {v0.x, v0.y, v0.z, v0.w, v1.x, v1.y, v1.z, v1.w};

#pragma unroll
    for (int e = 0; e < 8; ++e) {
        float acc = sbo[e];
#pragma unroll
        for (int j = 0; j < 8; ++j) acc = fmaf(o[j], sWo[e * 8 + j], acc);
        o2sh[w][lane * 8 + e] = acc;
    }
    __syncwarp();

    if (lane < 16) {
        float acc = sLb[lane];
#pragma unroll 8
        for (int i = 0; i < 256; ++i)
            acc = fmaf(o2sh[w][i], sLw[i * 16 + lane], acc);

        // softmax over 16 lanes
        float m = acc;
#pragma unroll
        for (int off = 8; off; off >>= 1)
            m = fmaxf(m, __shfl_xor_sync(0xffffu, m, off, 16));
        float e = __expf(acc - m);
        float s = e;
#pragma unroll
        for (int off = 8; off; off >>= 1)
            s += __shfl_xor_sync(0xffffu, s, off, 16);
        out[b * OUTD + lane] = e / s;
    }
}

// ---------------------------------------------------------------------------
extern "C" void kernel_launch(void* const* d_in, const int* in_sizes, int n_in,
                              void* d_out, int out_size) {
    const float* x   = (const float*)d_in[0];   // (1024, 32)
    const float* emb = (const float*)d_in[1];   // (32, 1100, 8)
    const float* ipw = (const float*)d_in[2];   // (24, 8)
    const float* ipb = (const float*)d_in[3];   // (24,)
    const float* opw = (const float*)d_in[4];   // (8, 8)
    const float* opb = (const float*)d_in[5];   // (8,)
    const float* lw  = (const float*)d_in[6];   // (16, 256)
    const float* lb  = (const float*)d_in[7];   // (16,)
    float* out = (float*)d_out;                 // (1024, 16)

    stageA<<<dim3(8, FDIM), 128>>>(x, emb, ipw, ipb);
    stageB<<<dim3(FH, BATCH / 128), 128>>>();
    stageC<<<BATCH / 16, 512>>>(opw, opb, lw, lb, out);
}